// round 8
// baseline (speedup 1.0000x reference)
#include <cuda_runtime.h>
#include <math_constants.h>

// DiceEmbedding fused single kernel:
//   out[n,e] = sum_d polar(v_n)[d] * (W@Q)[e,d] + b[e]
//   theta = log(0.01+|v|)/85*pi ; s=sin, c=cos
//   polar[j] = s^j * c (j=0..8), polar[9] = s^10
//
// R8: clean occupancy A/B. 2 output columns per thread (weights 20 regs)
// -> ~56 regs -> 4 CTAs/SM = 32 warps of store concurrency, while KEEPING
// the batched loop-top LDS structure (R5 showed serialized LDS is the
// thing that hurts, not occupancy itself... or so we test here).
// Each block: 256 rows x 512 cols; column half = blockIdx.x & 1.

#define EMB 1024
#define DPOL 10
#define RPB 256   // rows per block

__device__ __forceinline__ unsigned long long fma2(unsigned long long a,
                                                   unsigned long long b,
                                                   unsigned long long c) {
    unsigned long long d;
    asm("fma.rn.f32x2 %0, %1, %2, %3;" : "=l"(d) : "l"(a), "l"(b), "l"(c));
    return d;
}

__device__ __forceinline__ unsigned long long pack_dup(float x) {
    unsigned long long r;
    unsigned int u = __float_as_uint(x);
    asm("mov.b64 %0, {%1, %1};" : "=l"(r) : "r"(u));
    return r;
}

__device__ __forceinline__ unsigned long long pack2(float lo, float hi) {
    unsigned long long r;
    asm("mov.b64 %0, {%1, %2};" : "=l"(r) : "r"(__float_as_uint(lo)), "r"(__float_as_uint(hi)));
    return r;
}

__device__ __forceinline__ void unpack2(unsigned long long v, float& lo, float& hi) {
    unsigned int a, b;
    asm("mov.b64 {%0, %1}, %2;" : "=r"(a), "=r"(b) : "l"(v));
    lo = __uint_as_float(a);
    hi = __uint_as_float(b);
}

__global__ void __launch_bounds__(256, 4)
dice_fused_kernel(const float* __restrict__ bv,
                  const float* __restrict__ Qm,    // [10,10]
                  const float* __restrict__ W,     // [1024,10]
                  const float* __restrict__ bias,  // [1024]
                  float* __restrict__ out,
                  int N) {
    // polar values duplicated into both f32x2 lanes, [row][d]
    __shared__ __align__(16) unsigned long long spolar[RPB][DPOL];
    __shared__ float sQ[DPOL * DPOL];

    const int t = threadIdx.x;
    const int colHalf = blockIdx.x & 1;             // 0 or 1
    const int rowBase = (blockIdx.x >> 1) * RPB;

    // stage Q for broadcast
    if (t < DPOL * DPOL) sQ[t] = Qm[t];
    __syncthreads();   // sQ ready

    // ---- phase 1: each thread computes polar for one row, writes smem ----
    {
        int r = rowBase + t;
        float v = (r < N) ? bv[r] : 0.f;
        const float k = (float)(CUDART_PI / 85.0);
        float theta = __logf(0.01f + fabsf(v)) * k;
        float s, c;
        __sincosf(theta, &s, &c);
        float p = c;
#pragma unroll
        for (int j = 0; j < 9; j++) {
            spolar[t][j] = pack_dup(p);
            p *= s;
        }
        float s2 = s * s;
        float s4 = s2 * s2;
        float s8 = s4 * s4;
        spolar[t][9] = pack_dup(s8 * s2);   // polar[9] = s^10
    }

    // ---- fold WQ for this thread's 2 output columns (no spolar dep;
    //      overlaps other warps reaching the barrier) ----
    const int c0 = colHalf * (EMB / 2) + t * 2;
    unsigned long long wq[DPOL];
    {
        float d0[DPOL], d1[DPOL];
#pragma unroll
        for (int d = 0; d < DPOL; d++) { d0[d] = 0.f; d1[d] = 0.f; }
#pragma unroll
        for (int k = 0; k < DPOL; k++) {
            float w0 = W[(c0 + 0) * DPOL + k];
            float w1 = W[(c0 + 1) * DPOL + k];
#pragma unroll
            for (int d = 0; d < DPOL; d++) {
                float q = sQ[k * DPOL + d];
                d0[d] = fmaf(w0, q, d0[d]);
                d1[d] = fmaf(w1, q, d1[d]);
            }
        }
#pragma unroll
        for (int d = 0; d < DPOL; d++) wq[d] = pack2(d0[d], d1[d]);
    }

    // bias pair for this thread's 2 columns
    const unsigned long long bb =
        *reinterpret_cast<const unsigned long long*>(&bias[c0]);

    __syncthreads();   // spolar ready

    const int nr = min(RPB, N - rowBase);
    float2* outp = reinterpret_cast<float2*>(out) +
                   (size_t)rowBase * (EMB / 2) + colHalf * (EMB / 4) + t;
    // note: EMB/2 float2 per row; this block's half starts at colHalf*(EMB/4)
    // float2 elements... careful: c0 in floats = colHalf*512 + t*2 ->
    // in float2 units = colHalf*256 + t. EMB/4 = 256. OK.

    // ---- phase 2: each row, every thread emits 2 contiguous fp32 outputs.
    //      All 5 spolar chunks loaded at loop top for MLP. ----
    for (int r = 0; r < nr; r++) {
        const ulonglong2* sp = reinterpret_cast<const ulonglong2*>(&spolar[r][0]);
        ulonglong2 q0 = sp[0];  // d0,d1
        ulonglong2 q1 = sp[1];  // d2,d3
        ulonglong2 q2 = sp[2];  // d4,d5
        ulonglong2 q3 = sp[3];  // d6,d7
        ulonglong2 q4 = sp[4];  // d8,d9

        unsigned long long a = bb;
        a = fma2(q0.x, wq[0], a);
        a = fma2(q0.y, wq[1], a);
        a = fma2(q1.x, wq[2], a);
        a = fma2(q1.y, wq[3], a);
        a = fma2(q2.x, wq[4], a);
        a = fma2(q2.y, wq[5], a);
        a = fma2(q3.x, wq[6], a);
        a = fma2(q3.y, wq[7], a);
        a = fma2(q4.x, wq[8], a);
        a = fma2(q4.y, wq[9], a);

        float2 o;
        unpack2(a, o.x, o.y);
        *outp = o;
        outp += EMB / 2;
    }
}

extern "C" void kernel_launch(void* const* d_in, const int* in_sizes, int n_in,
                              void* d_out, int out_size) {
    const float* bv = (const float*)d_in[0];   // [N]
    const float* Q  = (const float*)d_in[1];   // [10,10]
    const float* W  = (const float*)d_in[2];   // [1024,10]
    const float* b  = (const float*)d_in[3];   // [1024]
    float* out = (float*)d_out;
    const int N = in_sizes[0];

    int nrowblocks = (N + RPB - 1) / RPB;
    dice_fused_kernel<<<nrowblocks * 2, 256>>>(bv, Q, W, b, out, N);
}

// round 9
// speedup vs baseline: 1.1091x; 1.1091x over previous
#include <cuda_runtime.h>
#include <math_constants.h>

// DiceEmbedding fused single kernel (FINAL = R4 structure, measured champion):
//   out[n,e] = sum_d polar(v_n)[d] * (W@Q)[e,d] + b[e]
//   theta = log(0.01+|v|)/85*pi ; s=sin, c=cos
//   polar[j] = s^j * c (j=0..8), polar[9] = s^10
//
// Design record (8 rounds of A/B on GB300):
//  - 4 output cols/thread: balances LDS bytes/stored byte (80/16); 2 cols
//    saturates L1 (93%) and starves DRAM (R8).
//  - 3 CTAs/SM @ 80 regs beats 4 CTAs @ 64: intra-warp MLP from batched
//    loop-top LDS.128 is worth more than warps (R5, R8).
//  - Default write-back stores; .cs eager eviction breaks the L2 write
//    drain (-6% DRAM, R3).
//  - W@Q folded per-thread before the barrier; fold hides in barrier wait.
//  - Kernel sits at the HBM3e pure-write ceiling: ~6.55 TB/s (82% of spec).

#define EMB 1024
#define DPOL 10
#define RPB 256   // rows per block

__device__ __forceinline__ unsigned long long fma2(unsigned long long a,
                                                   unsigned long long b,
                                                   unsigned long long c) {
    unsigned long long d;
    asm("fma.rn.f32x2 %0, %1, %2, %3;" : "=l"(d) : "l"(a), "l"(b), "l"(c));
    return d;
}

__device__ __forceinline__ unsigned long long pack_dup(float x) {
    unsigned long long r;
    unsigned int u = __float_as_uint(x);
    asm("mov.b64 %0, {%1, %1};" : "=l"(r) : "r"(u));
    return r;
}

__device__ __forceinline__ unsigned long long pack2(float lo, float hi) {
    unsigned long long r;
    asm("mov.b64 %0, {%1, %2};" : "=l"(r) : "r"(__float_as_uint(lo)), "r"(__float_as_uint(hi)));
    return r;
}

__device__ __forceinline__ void unpack2(unsigned long long v, float& lo, float& hi) {
    unsigned int a, b;
    asm("mov.b64 {%0, %1}, %2;" : "=r"(a), "=r"(b) : "l"(v));
    lo = __uint_as_float(a);
    hi = __uint_as_float(b);
}

__global__ void __launch_bounds__(256, 3)
dice_fused_kernel(const float* __restrict__ bv,
                  const float* __restrict__ Qm,    // [10,10]
                  const float* __restrict__ W,     // [1024,10]
                  const float* __restrict__ bias,  // [1024]
                  float* __restrict__ out,
                  int N) {
    // polar values duplicated into both f32x2 lanes, [row][d]
    __shared__ __align__(16) unsigned long long spolar[RPB][DPOL];
    __shared__ float sQ[DPOL * DPOL];

    const int t = threadIdx.x;
    const int rowBase = blockIdx.x * RPB;

    // stage Q for broadcast
    if (t < DPOL * DPOL) sQ[t] = Qm[t];
    __syncthreads();   // sQ ready

    // ---- phase 1: each thread computes polar for one row, writes smem ----
    {
        int r = rowBase + t;
        float v = (r < N) ? bv[r] : 0.f;
        const float k = (float)(CUDART_PI / 85.0);
        float theta = __logf(0.01f + fabsf(v)) * k;
        float s, c;
        __sincosf(theta, &s, &c);
        float p = c;
#pragma unroll
        for (int j = 0; j < 9; j++) {
            spolar[t][j] = pack_dup(p);
            p *= s;
        }
        float s2 = s * s;
        float s4 = s2 * s2;
        float s8 = s4 * s4;
        spolar[t][9] = pack_dup(s8 * s2);   // polar[9] = s^10
    }

    // ---- fold WQ for this thread's 4 output columns (independent of
    //      spolar, so it executes while other warps reach the barrier) ----
    const int c0 = t * 4;
    unsigned long long wqa[DPOL], wqb[DPOL];
    {
        float d0[DPOL], d1[DPOL];
#pragma unroll
        for (int d = 0; d < DPOL; d++) { d0[d] = 0.f; d1[d] = 0.f; }
#pragma unroll
        for (int k = 0; k < DPOL; k++) {
            float w0 = W[(c0 + 0) * DPOL + k];
            float w1 = W[(c0 + 1) * DPOL + k];
#pragma unroll
            for (int d = 0; d < DPOL; d++) {
                float q = sQ[k * DPOL + d];
                d0[d] = fmaf(w0, q, d0[d]);
                d1[d] = fmaf(w1, q, d1[d]);
            }
        }
#pragma unroll
        for (int d = 0; d < DPOL; d++) wqa[d] = pack2(d0[d], d1[d]);
#pragma unroll
        for (int d = 0; d < DPOL; d++) { d0[d] = 0.f; d1[d] = 0.f; }
#pragma unroll
        for (int k = 0; k < DPOL; k++) {
            float w2 = W[(c0 + 2) * DPOL + k];
            float w3 = W[(c0 + 3) * DPOL + k];
#pragma unroll
            for (int d = 0; d < DPOL; d++) {
                float q = sQ[k * DPOL + d];
                d0[d] = fmaf(w2, q, d0[d]);
                d1[d] = fmaf(w3, q, d1[d]);
            }
        }
#pragma unroll
        for (int d = 0; d < DPOL; d++) wqb[d] = pack2(d0[d], d1[d]);
    }

    ulonglong2 b2 = *reinterpret_cast<const ulonglong2*>(&bias[c0]);
    const unsigned long long ba = b2.x, bb = b2.y;

    __syncthreads();   // spolar ready

    const int nr = min(RPB, N - rowBase);

    // ---- phase 2: each row, every thread emits 4 contiguous fp32 outputs ----
    for (int r = 0; r < nr; r++) {
        const ulonglong2* sp = reinterpret_cast<const ulonglong2*>(&spolar[r][0]);
        ulonglong2 q0 = sp[0];  // d0,d1
        ulonglong2 q1 = sp[1];  // d2,d3
        ulonglong2 q2 = sp[2];  // d4,d5
        ulonglong2 q3 = sp[3];  // d6,d7
        ulonglong2 q4 = sp[4];  // d8,d9

        unsigned long long a = ba, b = bb;
        a = fma2(q0.x, wqa[0], a);  b = fma2(q0.x, wqb[0], b);
        a = fma2(q0.y, wqa[1], a);  b = fma2(q0.y, wqb[1], b);
        a = fma2(q1.x, wqa[2], a);  b = fma2(q1.x, wqb[2], b);
        a = fma2(q1.y, wqa[3], a);  b = fma2(q1.y, wqb[3], b);
        a = fma2(q2.x, wqa[4], a);  b = fma2(q2.x, wqb[4], b);
        a = fma2(q2.y, wqa[5], a);  b = fma2(q2.y, wqb[5], b);
        a = fma2(q3.x, wqa[6], a);  b = fma2(q3.x, wqb[6], b);
        a = fma2(q3.y, wqa[7], a);  b = fma2(q3.y, wqb[7], b);
        a = fma2(q4.x, wqa[8], a);  b = fma2(q4.x, wqb[8], b);
        a = fma2(q4.y, wqa[9], a);  b = fma2(q4.y, wqb[9], b);

        float4 o;
        unpack2(a, o.x, o.y);
        unpack2(b, o.z, o.w);
        reinterpret_cast<float4*>(out)[(size_t)(rowBase + r) * (EMB / 4) + t] = o;
    }
}

extern "C" void kernel_launch(void* const* d_in, const int* in_sizes, int n_in,
                              void* d_out, int out_size) {
    const float* bv = (const float*)d_in[0];   // [N]
    const float* Q  = (const float*)d_in[1];   // [10,10]
    const float* W  = (const float*)d_in[2];   // [1024,10]
    const float* b  = (const float*)d_in[3];   // [1024]
    float* out = (float*)d_out;
    const int N = in_sizes[0];

    int nblocks = (N + RPB - 1) / RPB;
    dice_fused_kernel<<<nblocks, 256>>>(bv, Q, W, b, out, N);
}

// round 10
// speedup vs baseline: 1.1636x; 1.0492x over previous
#include <cuda_runtime.h>
#include <math_constants.h>

// DiceEmbedding fused single kernel (FINAL = R4 structure, measured champion):
//   out[n,e] = sum_d polar(v_n)[d] * (W@Q)[e,d] + b[e]
//   theta = log(0.01+|v|)/85*pi ; s=sin, c=cos
//   polar[j] = s^j * c (j=0..8), polar[9] = s^10
//
// Design record (9 rounds of A/B on GB300):
//  - 4 output cols/thread: balances LDS bytes/stored byte (80/16); 2 cols
//    saturates L1 (93%) and starves DRAM (R8).
//  - 3 CTAs/SM @ 80 regs beats 4 CTAs @ 64: intra-warp MLP from batched
//    loop-top LDS.128 is worth more than warps (R5, R8).
//  - Default write-back stores; .cs eager eviction breaks the L2 write
//    drain (-6% DRAM, R3).
//  - W@Q folded per-thread before the barrier; fold hides in barrier wait.
//  - Kernel sits at the HBM3e pure-write ceiling (~6.5 TB/s sustained).
//  - R9 == R4 source measured 166 vs 155 us: broker-pool run-to-run noise
//    is +/-4-5%; structural tuning below that band is not meaningful.

#define EMB 1024
#define DPOL 10
#define RPB 256   // rows per block

__device__ __forceinline__ unsigned long long fma2(unsigned long long a,
                                                   unsigned long long b,
                                                   unsigned long long c) {
    unsigned long long d;
    asm("fma.rn.f32x2 %0, %1, %2, %3;" : "=l"(d) : "l"(a), "l"(b), "l"(c));
    return d;
}

__device__ __forceinline__ unsigned long long pack_dup(float x) {
    unsigned long long r;
    unsigned int u = __float_as_uint(x);
    asm("mov.b64 %0, {%1, %1};" : "=l"(r) : "r"(u));
    return r;
}

__device__ __forceinline__ unsigned long long pack2(float lo, float hi) {
    unsigned long long r;
    asm("mov.b64 %0, {%1, %2};" : "=l"(r) : "r"(__float_as_uint(lo)), "r"(__float_as_uint(hi)));
    return r;
}

__device__ __forceinline__ void unpack2(unsigned long long v, float& lo, float& hi) {
    unsigned int a, b;
    asm("mov.b64 {%0, %1}, %2;" : "=r"(a), "=r"(b) : "l"(v));
    lo = __uint_as_float(a);
    hi = __uint_as_float(b);
}

__global__ void __launch_bounds__(256, 3)
dice_fused_kernel(const float* __restrict__ bv,
                  const float* __restrict__ Qm,    // [10,10]
                  const float* __restrict__ W,     // [1024,10]
                  const float* __restrict__ bias,  // [1024]
                  float* __restrict__ out,
                  int N) {
    // polar values duplicated into both f32x2 lanes, [row][d]
    __shared__ __align__(16) unsigned long long spolar[RPB][DPOL];
    __shared__ float sQ[DPOL * DPOL];

    const int t = threadIdx.x;
    const int rowBase = blockIdx.x * RPB;

    // stage Q for broadcast
    if (t < DPOL * DPOL) sQ[t] = Qm[t];
    __syncthreads();   // sQ ready

    // ---- phase 1: each thread computes polar for one row, writes smem ----
    {
        int r = rowBase + t;
        float v = (r < N) ? bv[r] : 0.f;
        const float k = (float)(CUDART_PI / 85.0);
        float theta = __logf(0.01f + fabsf(v)) * k;
        float s, c;
        __sincosf(theta, &s, &c);
        float p = c;
#pragma unroll
        for (int j = 0; j < 9; j++) {
            spolar[t][j] = pack_dup(p);
            p *= s;
        }
        float s2 = s * s;
        float s4 = s2 * s2;
        float s8 = s4 * s4;
        spolar[t][9] = pack_dup(s8 * s2);   // polar[9] = s^10
    }

    // ---- fold WQ for this thread's 4 output columns (independent of
    //      spolar, so it executes while other warps reach the barrier) ----
    const int c0 = t * 4;
    unsigned long long wqa[DPOL], wqb[DPOL];
    {
        float d0[DPOL], d1[DPOL];
#pragma unroll
        for (int d = 0; d < DPOL; d++) { d0[d] = 0.f; d1[d] = 0.f; }
#pragma unroll
        for (int k = 0; k < DPOL; k++) {
            float w0 = W[(c0 + 0) * DPOL + k];
            float w1 = W[(c0 + 1) * DPOL + k];
#pragma unroll
            for (int d = 0; d < DPOL; d++) {
                float q = sQ[k * DPOL + d];
                d0[d] = fmaf(w0, q, d0[d]);
                d1[d] = fmaf(w1, q, d1[d]);
            }
        }
#pragma unroll
        for (int d = 0; d < DPOL; d++) wqa[d] = pack2(d0[d], d1[d]);
#pragma unroll
        for (int d = 0; d < DPOL; d++) { d0[d] = 0.f; d1[d] = 0.f; }
#pragma unroll
        for (int k = 0; k < DPOL; k++) {
            float w2 = W[(c0 + 2) * DPOL + k];
            float w3 = W[(c0 + 3) * DPOL + k];
#pragma unroll
            for (int d = 0; d < DPOL; d++) {
                float q = sQ[k * DPOL + d];
                d0[d] = fmaf(w2, q, d0[d]);
                d1[d] = fmaf(w3, q, d1[d]);
            }
        }
#pragma unroll
        for (int d = 0; d < DPOL; d++) wqb[d] = pack2(d0[d], d1[d]);
    }

    ulonglong2 b2 = *reinterpret_cast<const ulonglong2*>(&bias[c0]);
    const unsigned long long ba = b2.x, bb = b2.y;

    __syncthreads();   // spolar ready

    const int nr = min(RPB, N - rowBase);

    // ---- phase 2: each row, every thread emits 4 contiguous fp32 outputs ----
    for (int r = 0; r < nr; r++) {
        const ulonglong2* sp = reinterpret_cast<const ulonglong2*>(&spolar[r][0]);
        ulonglong2 q0 = sp[0];  // d0,d1
        ulonglong2 q1 = sp[1];  // d2,d3
        ulonglong2 q2 = sp[2];  // d4,d5
        ulonglong2 q3 = sp[3];  // d6,d7
        ulonglong2 q4 = sp[4];  // d8,d9

        unsigned long long a = ba, b = bb;
        a = fma2(q0.x, wqa[0], a);  b = fma2(q0.x, wqb[0], b);
        a = fma2(q0.y, wqa[1], a);  b = fma2(q0.y, wqb[1], b);
        a = fma2(q1.x, wqa[2], a);  b = fma2(q1.x, wqb[2], b);
        a = fma2(q1.y, wqa[3], a);  b = fma2(q1.y, wqb[3], b);
        a = fma2(q2.x, wqa[4], a);  b = fma2(q2.x, wqb[4], b);
        a = fma2(q2.y, wqa[5], a);  b = fma2(q2.y, wqb[5], b);
        a = fma2(q3.x, wqa[6], a);  b = fma2(q3.x, wqb[6], b);
        a = fma2(q3.y, wqa[7], a);  b = fma2(q3.y, wqb[7], b);
        a = fma2(q4.x, wqa[8], a);  b = fma2(q4.x, wqb[8], b);
        a = fma2(q4.y, wqa[9], a);  b = fma2(q4.y, wqb[9], b);

        float4 o;
        unpack2(a, o.x, o.y);
        unpack2(b, o.z, o.w);
        reinterpret_cast<float4*>(out)[(size_t)(rowBase + r) * (EMB / 4) + t] = o;
    }
}

extern "C" void kernel_launch(void* const* d_in, const int* in_sizes, int n_in,
                              void* d_out, int out_size) {
    const float* bv = (const float*)d_in[0];   // [N]
    const float* Q  = (const float*)d_in[1];   // [10,10]
    const float* W  = (const float*)d_in[2];   // [1024,10]
    const float* b  = (const float*)d_in[3];   // [1024]
    float* out = (float*)d_out;
    const int N = in_sizes[0];

    int nblocks = (N + RPB - 1) / RPB;
    dice_fused_kernel<<<nblocks, 256>>>(bv, Q, W, b, out, N);
}